// round 15
// baseline (speedup 1.0000x reference)
#include <cuda_runtime.h>
#include <cuda_fp16.h>
#include <math.h>
#include <stdint.h>

#define BB 2
#define SS 2048
#define HH 1024
#define FF 2816
#define EE 8
#define KK 2
#define TT (BB*SS)
#define SLOTS (TT*KK)
#define BM 128
#define PADMAX (SLOTS + EE*BM)    // 9216
#define RT_MAX (PADMAX/BM)        // 72
#define PITA 132                  // uint2 pitch (A): 2*132 mod 32 == 8 -> conflict-free
#define PITB 136                  // uint pitch (B): 136 mod 32 == 8 -> conflict-free

__device__ float g_h1[(size_t)PADMAX * FF];
__device__ float g_y [(size_t)PADMAX * HH];
__device__ int   g_count[EE];
__device__ int   g_fill[EE];
__device__ float g_psum[EE];
__device__ int   g_base[EE+1];
__device__ int   g_sorted_token[PADMAX];
__device__ int   g_slot_row[SLOTS];
__device__ int   g_tok_e[SLOTS];
__device__ float g_tok_w[SLOTS];

__device__ __forceinline__ void hsplit(float v, unsigned short& h, unsigned short& l) {
    __half hh = __float2half(v);
    __half ll = __float2half((v - __half2float(hh)) * 2048.f);
    h = __half_as_ushort(hh); l = __half_as_ushort(ll);
}
__device__ __forceinline__ uint32_t pk(unsigned short lo, unsigned short hi) {
    return (uint32_t)lo | ((uint32_t)hi << 16);
}
// A word pair: (.x = (Ah_e, Ah_o), .y = (Al2_e, Al2_o))
__device__ __forceinline__ uint2 sph(float x, float y) {
    unsigned short hx, lx, hy, ly;
    hsplit(x, hx, lx); hsplit(y, hy, ly);
    return make_uint2(pk(hx, hy), pk(lx, ly));
}
__device__ __forceinline__ uint32_t prmt(uint32_t a, uint32_t b, uint32_t s) {
    uint32_t r; asm("prmt.b32 %0, %1, %2, %3;" : "=r"(r) : "r"(a), "r"(b), "r"(s)); return r;
}
__device__ __forceinline__ void mma_f32(float* d, const uint32_t* a, uint32_t b0, uint32_t b1) {
    asm volatile("mma.sync.aligned.m16n8k16.row.col.f32.f16.f16.f32 "
                 "{%0,%1,%2,%3}, {%4,%5,%6,%7}, {%8,%9}, {%0,%1,%2,%3};"
                 : "+f"(d[0]), "+f"(d[1]), "+f"(d[2]), "+f"(d[3])
                 : "r"(a[0]), "r"(a[1]), "r"(a[2]), "r"(a[3]), "r"(b0), "r"(b1));
}
__device__ __forceinline__ void mma_f16(uint32_t* d, const uint32_t* a, uint32_t b0, uint32_t b1) {
    asm volatile("mma.sync.aligned.m16n8k16.row.col.f16.f16.f16.f16 "
                 "{%0,%1}, {%2,%3,%4,%5}, {%6,%7}, {%0,%1};"
                 : "+r"(d[0]), "+r"(d[1])
                 : "r"(a[0]), "r"(a[1]), "r"(a[2]), "r"(a[3]), "r"(b0), "r"(b1));
}

__global__ void init_kernel() {
    int i = blockIdx.x * blockDim.x + threadIdx.x;
    if (i < PADMAX) g_sorted_token[i] = 0;
    if (i < EE) { g_count[i] = 0; g_fill[i] = 0; g_psum[i] = 0.f; }
}

__global__ void router_kernel(const float* __restrict__ x, const float* __restrict__ rw) {
    int t = blockIdx.x;
    __shared__ float sp[128][EE];
    float acc[EE];
#pragma unroll
    for (int e = 0; e < EE; e++) acc[e] = 0.f;
    const float* xt = x + (size_t)t * HH;
    for (int h = threadIdx.x; h < HH; h += 128) {
        float xv = xt[h];
#pragma unroll
        for (int e = 0; e < EE; e++) acc[e] += xv * rw[e*HH + h];
    }
#pragma unroll
    for (int e = 0; e < EE; e++) sp[threadIdx.x][e] = acc[e];
    __syncthreads();
    for (int s = 64; s > 0; s >>= 1) {
        if (threadIdx.x < s)
#pragma unroll
            for (int e = 0; e < EE; e++) sp[threadIdx.x][e] += sp[threadIdx.x + s][e];
        __syncthreads();
    }
    if (threadIdx.x == 0) {
        float lg[EE];
#pragma unroll
        for (int e = 0; e < EE; e++) lg[e] = sp[0][e];
        int i0 = 0;
#pragma unroll
        for (int e = 1; e < EE; e++) if (lg[e] > lg[i0]) i0 = e;
        int i1 = -1;
#pragma unroll
        for (int e = 0; e < EE; e++) {
            if (e == i0) continue;
            if (i1 < 0 || lg[e] > lg[i1]) i1 = e;
        }
        float ex = expf(lg[i1] - lg[i0]);
        g_tok_e[2*t] = i0;  g_tok_e[2*t+1] = i1;
        g_tok_w[2*t] = 1.f/(1.f+ex);  g_tok_w[2*t+1] = ex/(1.f+ex);
        atomicAdd(&g_count[i0], 1);
        atomicAdd(&g_count[i1], 1);
        float m = lg[0];
#pragma unroll
        for (int e = 1; e < EE; e++) m = fmaxf(m, lg[e]);
        float s = 0.f, pe[EE];
#pragma unroll
        for (int e = 0; e < EE; e++) { pe[e] = expf(lg[e] - m); s += pe[e]; }
        float inv = 1.f / s;
#pragma unroll
        for (int e = 0; e < EE; e++) atomicAdd(&g_psum[e], pe[e] * inv);
    }
}

__global__ void setup_kernel(float* __restrict__ out_aux) {
    if (threadIdx.x == 0) {
        int base = 0;
        for (int e = 0; e < EE; e++) {
            g_base[e] = base;
            base += (g_count[e] + BM - 1) & ~(BM - 1);
        }
        g_base[EE] = base;
        float aux = 0.f;
        for (int e = 0; e < EE; e++)
            aux += ((float)g_count[e] / SLOTS) * (g_psum[e] / TT);
        out_aux[0] = aux * EE;
    }
}

__global__ void scatter_kernel() {
    int s = blockIdx.x * blockDim.x + threadIdx.x;
    if (s >= SLOTS) return;
    int e = g_tok_e[s];
    int row = g_base[e] + atomicAdd(&g_fill[e], 1);
    g_sorted_token[row] = s >> 1;
    g_slot_row[s] = row;
}

#define CROSS_SCALE (1.f/2048.f)

// ==== GEMM1: h1 = silu(x@Wg)*(x@Wu). 256 thr, CTA 128M x 32F (64 interleaved cols) ====
__global__ __launch_bounds__(256, 2) void gemm1_kernel(
    const float* __restrict__ x, const float* __restrict__ wg, const float* __restrict__ wu)
{
    int r0 = blockIdx.x * BM;
    if (r0 >= g_base[EE]) return;
    int n0f = blockIdx.y * 32;
    int e = 0;
    while (g_base[e+1] <= r0) e++;

    __shared__ __align__(16) uint2 As[2][8][PITA];
    __shared__ __align__(16) uint32_t Bm[2][8][PITB];
    __shared__ __align__(16) uint32_t Bc[2][16][PITB];
    __shared__ int s_tok[128];

    int tid = threadIdx.x, lane = tid & 31, wid = tid >> 5;
    if (tid < 128) s_tok[tid] = g_sorted_token[r0 + tid];
    __syncthreads();

    int wm = (wid >> 1) * 32, wn = (wid & 1) * 32;
    int fr = lane >> 2, kq = lane & 3;
    int hsel = kq & 1, pbase = kq >> 1;
    uint32_t psel = hsel ? 0x7632u : 0x5410u;

    int a_row = tid & 127, a_kh = tid >> 7;
    const float* arow = x + (size_t)s_tok[a_row] * HH + a_kh * 8;
    int b_kp = tid >> 5, feat = tid & 31;
    const float* gptr = wg + (size_t)e * HH * FF + n0f + feat;
    const float* uptr = wu + (size_t)e * HH * FF + n0f + feat;

    float dmn[2][4][4];
    uint32_t dc[2][4][2];
#pragma unroll
    for (int i = 0; i < 2; i++)
#pragma unroll
        for (int j = 0; j < 4; j++) {
#pragma unroll
            for (int k = 0; k < 4; k++) dmn[i][j][k] = 0.f;
            dc[i][j][0] = 0u; dc[i][j][1] = 0u;
        }

#define G1_STS(st, A0, A1, G0, G1v, U0, U1v) do {                               \
    float af_[8] = {(A0).x,(A0).y,(A0).z,(A0).w,(A1).x,(A1).y,(A1).z,(A1).w};   \
    _Pragma("unroll")                                                           \
    for (int j_ = 0; j_ < 4; j_++)                                              \
        As[st][a_kh*4 + j_][a_row] = sph(af_[2*j_], af_[2*j_+1]);               \
    unsigned short hg0,lg0,hg1,lg1,hu0,lu0,hu1,lu1;                             \
    hsplit(G0,hg0,lg0); hsplit(G1v,hg1,lg1);                                    \
    hsplit(U0,hu0,lu0); hsplit(U1v,hu1,lu1);                                    \
    *(uint2*)&Bm[st][b_kp][2*feat]     = make_uint2(pk(hg0,hg1), pk(hu0,hu1));  \
    *(uint2*)&Bc[st][2*b_kp][2*feat]   = make_uint2(pk(lg0,hg0), pk(lu0,hu0));  \
    *(uint2*)&Bc[st][2*b_kp+1][2*feat] = make_uint2(pk(lg1,hg1), pk(lu1,hu1));  \
} while (0)

    {
        float4 a0 = *(const float4*)(arow), a1 = *(const float4*)(arow + 4);
        size_t k0 = (size_t)(2*b_kp) * FF;
        float g0 = gptr[k0], g1 = gptr[k0 + FF];
        float u0 = uptr[k0], u1 = uptr[k0 + FF];
        G1_STS(0, a0, a1, g0, g1, u0, u1);
    }
    float4 pa0 = *(const float4*)(arow + 16), pa1 = *(const float4*)(arow + 20);
    float pg0, pg1, pu0, pu1;
    {
        size_t k0 = (size_t)(16 + 2*b_kp) * FF;
        pg0 = gptr[k0]; pg1 = gptr[k0 + FF];
        pu0 = uptr[k0]; pu1 = uptr[k0 + FF];
    }
    __syncthreads();

    const int chunks = HH / 16;   // 64
    for (int c = 0; c < chunks; c++) {
        int s = c & 1;
        if (c + 1 < chunks) {
            int s1 = s ^ 1;
            G1_STS(s1, pa0, pa1, pg0, pg1, pu0, pu1);
        }
        if (c + 2 < chunks) {
            pa0 = *(const float4*)(arow + (c+2)*16);
            pa1 = *(const float4*)(arow + (c+2)*16 + 4);
            size_t k0 = (size_t)((c+2)*16 + 2*b_kp) * FF;
            pg0 = gptr[k0]; pg1 = gptr[k0 + FF];
            pu0 = uptr[k0]; pu1 = uptr[k0 + FF];
        }
        // main
        uint32_t am[2][4];
#pragma unroll
        for (int mt = 0; mt < 2; mt++) {
            int mb = wm + mt*16 + fr;
            am[mt][0] = As[s][kq][mb].x;   am[mt][1] = As[s][kq][mb+8].x;
            am[mt][2] = As[s][kq+4][mb].x; am[mt][3] = As[s][kq+4][mb+8].x;
        }
#pragma unroll
        for (int nt = 0; nt < 4; nt++) {
            int nn = wn + nt*8 + fr;
            uint32_t bm0 = Bm[s][kq][nn], bm1 = Bm[s][kq+4][nn];
#pragma unroll
            for (int mt = 0; mt < 2; mt++)
                mma_f32(dmn[mt][nt], am[mt], bm0, bm1);
        }
        // cross (two aug-k16 groups)
#pragma unroll
        for (int g = 0; g < 2; g++) {
            uint32_t ac[2][4];
#pragma unroll
            for (int mt = 0; mt < 2; mt++) {
                int mb = wm + mt*16 + fr;
                uint2 w0 = As[s][g*4 + pbase][mb],     w1 = As[s][g*4 + pbase][mb+8];
                uint2 w2 = As[s][g*4 + pbase + 2][mb], w3 = As[s][g*4 + pbase + 2][mb+8];
                ac[mt][0] = prmt(w0.x, w0.y, psel);
                ac[mt][1] = prmt(w1.x, w1.y, psel);
                ac[mt][2] = prmt(w2.x, w2.y, psel);
                ac[mt][3] = prmt(w3.x, w3.y, psel);
            }
#pragma unroll
            for (int nt = 0; nt < 4; nt++) {
                int nn = wn + nt*8 + fr;
                uint32_t bc0 = Bc[s][g*8 + kq][nn], bc1 = Bc[s][g*8 + kq + 4][nn];
#pragma unroll
                for (int mt = 0; mt < 2; mt++)
                    mma_f16(dc[mt][nt], ac[mt], bc0, bc1);
            }
        }
        __syncthreads();
    }
#undef G1_STS

#pragma unroll
    for (int mt = 0; mt < 2; mt++) {
        int row = r0 + wm + mt*16 + fr;
#pragma unroll
        for (int nt = 0; nt < 4; nt++) {
            int f = n0f + (wn >> 1) + nt*4 + kq;
            float2 c0 = __half22float2(*(__half2*)&dc[mt][nt][0]);
            float2 c1 = __half22float2(*(__half2*)&dc[mt][nt][1]);
            float gv = dmn[mt][nt][0] + c0.x * CROSS_SCALE;
            float uv = dmn[mt][nt][1] + c0.y * CROSS_SCALE;
            g_h1[(size_t)row * FF + f] = (gv / (1.f + expf(-gv))) * uv;
            gv = dmn[mt][nt][2] + c1.x * CROSS_SCALE;
            uv = dmn[mt][nt][3] + c1.y * CROSS_SCALE;
            g_h1[(size_t)(row + 8) * FF + f] = (gv / (1.f + expf(-gv))) * uv;
        }
    }
}

// ==== GEMM2: y = h1 @ Wd. 256 thr, CTA 128M x 64N ====
__global__ __launch_bounds__(256, 2) void gemm2_kernel(const float* __restrict__ wd)
{
    int r0 = blockIdx.x * BM;
    if (r0 >= g_base[EE]) return;
    int n0 = blockIdx.y * 64;
    int e = 0;
    while (g_base[e+1] <= r0) e++;

    __shared__ __align__(16) uint2 As[2][8][PITA];
    __shared__ __align__(16) uint32_t Bm[2][8][PITB];
    __shared__ __align__(16) uint32_t Bc[2][16][PITB];

    int tid = threadIdx.x, lane = tid & 31, wid = tid >> 5;
    int wm = (wid >> 1) * 32, wn = (wid & 1) * 32;
    int fr = lane >> 2, kq = lane & 3;
    int hsel = kq & 1, pbase = kq >> 1;
    uint32_t psel = hsel ? 0x7632u : 0x5410u;

    int a_row = tid & 127, a_kh = tid >> 7;
    const float* arow = g_h1 + (size_t)(r0 + a_row) * FF + a_kh * 8;
    int b_kp = tid >> 5, b_n = (tid & 31) * 2;
    const float* bptr = wd + (size_t)e * FF * HH + n0 + b_n;

    float dmn[2][4][4];
    uint32_t dc[2][4][2];
#pragma unroll
    for (int i = 0; i < 2; i++)
#pragma unroll
        for (int j = 0; j < 4; j++) {
#pragma unroll
            for (int k = 0; k < 4; k++) dmn[i][j][k] = 0.f;
            dc[i][j][0] = 0u; dc[i][j][1] = 0u;
        }

#define G2_STS(st, A0, A1, B0, B1v) do {                                        \
    float af_[8] = {(A0).x,(A0).y,(A0).z,(A0).w,(A1).x,(A1).y,(A1).z,(A1).w};   \
    _Pragma("unroll")                                                           \
    for (int j_ = 0; j_ < 4; j_++)                                              \
        As[st][a_kh*4 + j_][a_row] = sph(af_[2*j_], af_[2*j_+1]);               \
    unsigned short h0x,l0x,h0y,l0y,h1x,l1x,h1y,l1y;                             \
    hsplit((B0).x,h0x,l0x); hsplit((B0).y,h0y,l0y);                             \
    hsplit((B1v).x,h1x,l1x); hsplit((B1v).y,h1y,l1y);                           \
    *(uint2*)&Bm[st][b_kp][b_n]     = make_uint2(pk(h0x,h1x), pk(h0y,h1y));     \
    *(uint2*)&Bc[st][2*b_kp][b_n]   = make_uint2(pk(l0x,h0x), pk(l0y,h0y));     \
    *(uint2*)&Bc[st][2*b_kp+1][b_n] = make_uint2(pk(l1x,h1x), pk(l1y,h1y));     \
} while (0)

    {
        float4 a0 = *(const float4*)(arow), a1 = *(const float4*)(arow + 4);
        size_t k0 = (size_t)(2*b_kp) * HH;
        float2 b0 = *(const float2*)(bptr + k0), b1 = *(const float2*)(bptr + k0 + HH);
        G2_STS(0, a0, a1, b0, b1);
    }
    float4 pa0 = *(const float4*)(arow + 16), pa1 = *(const float4*)(arow + 20);
    float2 pb0, pb1;
    {
        size_t k0 = (size_t)(16 + 2*b_kp) * HH;
        pb0 = *(const float2*)(bptr + k0);  pb1 = *(const float2*)(bptr + k0 + HH);
    }
    __syncthreads();

    const int chunks = FF / 16;   // 176
    for (int c = 0; c < chunks; c++) {
        int s = c & 1;
        if (c + 1 < chunks) {
            int s1 = s ^ 1;
            G2_STS(s1, pa0, pa1, pb0, pb1);
        }
        if (c + 2 < chunks) {
            pa0 = *(const float4*)(arow + (c+2)*16);
            pa1 = *(const float4*)(arow + (c+2)*16 + 4);
            size_t k0 = (size_t)((c+2)*16 + 2*b_kp) * HH;
            pb0 = *(const float2*)(bptr + k0);
            pb1 = *(const float2*)(bptr + k0 + HH);
        }
        uint32_t am[2][4];
#pragma unroll
        for (int mt = 0; mt < 2; mt++) {
            int mb = wm + mt*16 + fr;
            am[mt][0] = As[s][kq][mb].x;   am[mt][1] = As[s][kq][mb+8].x;
            am[mt][2] = As[s][kq+4][mb].x; am[mt][3] = As[s][kq+4][mb+8].x;
        }
#pragma unroll
        for (int nt = 0; nt < 4; nt++) {
            int nn = wn + nt*8 + fr;
            uint32_t bm0 = Bm[s][kq][nn], bm1 = Bm[s][kq+4][nn];
#pragma unroll
            for (int mt = 0; mt < 2; mt++)
                mma_f32(dmn[mt][nt], am[mt], bm0, bm1);
        }
#pragma unroll
        for (int g = 0; g < 2; g++) {
            uint32_t ac[2][4];
#pragma unroll
            for (int mt = 0; mt < 2; mt++) {
                int mb = wm + mt*16 + fr;
                uint2 w0 = As[s][g*4 + pbase][mb],     w1 = As[s][g*4 + pbase][mb+8];
                uint2 w2 = As[s][g*4 + pbase + 2][mb], w3 = As[s][g*4 + pbase + 2][mb+8];
                ac[mt][0] = prmt(w0.x, w0.y, psel);
                ac[mt][1] = prmt(w1.x, w1.y, psel);
                ac[mt][2] = prmt(w2.x, w2.y, psel);
                ac[mt][3] = prmt(w3.x, w3.y, psel);
            }
#pragma unroll
            for (int nt = 0; nt < 4; nt++) {
                int nn = wn + nt*8 + fr;
                uint32_t bc0 = Bc[s][g*8 + kq][nn], bc1 = Bc[s][g*8 + kq + 4][nn];
#pragma unroll
                for (int mt = 0; mt < 2; mt++)
                    mma_f16(dc[mt][nt], ac[mt], bc0, bc1);
            }
        }
        __syncthreads();
    }
#undef G2_STS

#pragma unroll
    for (int mt = 0; mt < 2; mt++) {
        int row = r0 + wm + mt*16 + fr;
#pragma unroll
        for (int nt = 0; nt < 4; nt++) {
            int col = n0 + wn + nt*8 + 2*kq;
            float2 c0 = __half22float2(*(__half2*)&dc[mt][nt][0]);
            float2 c1 = __half22float2(*(__half2*)&dc[mt][nt][1]);
            float v0 = dmn[mt][nt][0] + c0.x * CROSS_SCALE;
            float v1 = dmn[mt][nt][1] + c0.y * CROSS_SCALE;
            *(float2*)&g_y[(size_t)row * HH + col] = make_float2(v0, v1);
            v0 = dmn[mt][nt][2] + c1.x * CROSS_SCALE;
            v1 = dmn[mt][nt][3] + c1.y * CROSS_SCALE;
            *(float2*)&g_y[(size_t)(row + 8) * HH + col] = make_float2(v0, v1);
        }
    }
}

__global__ void combine_kernel(float* __restrict__ out) {
    int i = blockIdx.x * blockDim.x + threadIdx.x;
    if (i >= TT * (HH/4)) return;
    int t = i / (HH/4);
    int c = (i - t * (HH/4)) * 4;
    int r0 = g_slot_row[2*t], r1 = g_slot_row[2*t+1];
    float w0 = g_tok_w[2*t], w1 = g_tok_w[2*t+1];
    float4 y0 = *(const float4*)(g_y + (size_t)r0 * HH + c);
    float4 y1 = *(const float4*)(g_y + (size_t)r1 * HH + c);
    float4 o;
    o.x = w0*y0.x + w1*y1.x;  o.y = w0*y0.y + w1*y1.y;
    o.z = w0*y0.z + w1*y1.z;  o.w = w0*y0.w + w1*y1.w;
    *(float4*)(out + (size_t)t * HH + c) = o;
}

extern "C" void kernel_launch(void* const* d_in, const int* in_sizes, int n_in,
                              void* d_out, int out_size) {
    const float* x  = (const float*)d_in[0];
    const float* rw = (const float*)d_in[1];
    const float* wg = (const float*)d_in[2];
    const float* wu = (const float*)d_in[3];
    const float* wd = (const float*)d_in[4];
    float* out = (float*)d_out;

    init_kernel<<<(PADMAX + 255) / 256, 256>>>();
    router_kernel<<<TT, 128>>>(x, rw);
    setup_kernel<<<1, 32>>>(out + (size_t)TT * HH);
    scatter_kernel<<<(SLOTS + 255) / 256, 256>>>();
    gemm1_kernel<<<dim3(RT_MAX, FF/32), 256>>>(x, wg, wu);
    gemm2_kernel<<<dim3(RT_MAX, HH/64), 256>>>(wd);
    combine_kernel<<<(TT * (HH/4) + 255) / 256, 256>>>(out);
}

// round 16
// speedup vs baseline: 1.4147x; 1.4147x over previous
#include <cuda_runtime.h>
#include <cuda_bf16.h>
#include <math.h>
#include <stdint.h>

#define BB 2
#define SS 2048
#define HH 1024
#define FF 2816
#define EE 8
#define KK 2
#define TT (BB*SS)
#define SLOTS (TT*KK)
#define BM 128
#define PADMAX (SLOTS + EE*BM)    // 9216
#define RT_MAX (PADMAX/BM)        // 72
#define PIT 132                   // uint2 pitch; 2*PIT mod 32 == 8 -> conflict-free fragment LDS
#define GRID_P 296                // 148 SMs x 2 CTAs

__device__ float g_h1[(size_t)PADMAX * FF];
__device__ float g_y [(size_t)PADMAX * HH];
__device__ int   g_count[EE];
__device__ int   g_fill[EE];
__device__ float g_psum[EE];
__device__ int   g_base[EE+1];
__device__ int   g_sorted_token[PADMAX];
__device__ int   g_slot_row[SLOTS];
__device__ int   g_tok_e[SLOTS];
__device__ float g_tok_w[SLOTS];

__device__ __forceinline__ uint2 spb(float x, float y) {
    __nv_bfloat16 hx = __float2bfloat16(x);
    __nv_bfloat16 hy = __float2bfloat16(y);
    __nv_bfloat16 lx = __float2bfloat16(x - __bfloat162float(hx));
    __nv_bfloat16 ly = __float2bfloat16(y - __bfloat162float(hy));
    uint2 r;
    r.x = (uint32_t)__bfloat16_as_ushort(hx) | ((uint32_t)__bfloat16_as_ushort(hy) << 16);
    r.y = (uint32_t)__bfloat16_as_ushort(lx) | ((uint32_t)__bfloat16_as_ushort(ly) << 16);
    return r;
}
__device__ __forceinline__ void mma_bf16(float* d, const uint32_t* a, uint32_t b0, uint32_t b1) {
    asm volatile("mma.sync.aligned.m16n8k16.row.col.f32.bf16.bf16.f32 "
                 "{%0,%1,%2,%3}, {%4,%5,%6,%7}, {%8,%9}, {%0,%1,%2,%3};"
                 : "+f"(d[0]), "+f"(d[1]), "+f"(d[2]), "+f"(d[3])
                 : "r"(a[0]), "r"(a[1]), "r"(a[2]), "r"(a[3]), "r"(b0), "r"(b1));
}

__global__ void init_kernel() {
    int i = blockIdx.x * blockDim.x + threadIdx.x;
    if (i < PADMAX) g_sorted_token[i] = 0;
    if (i < EE) { g_count[i] = 0; g_fill[i] = 0; g_psum[i] = 0.f; }
}

__global__ void router_kernel(const float* __restrict__ x, const float* __restrict__ rw) {
    int t = blockIdx.x;
    __shared__ float sp[128][EE];
    float acc[EE];
#pragma unroll
    for (int e = 0; e < EE; e++) acc[e] = 0.f;
    const float* xt = x + (size_t)t * HH;
    for (int h = threadIdx.x; h < HH; h += 128) {
        float xv = xt[h];
#pragma unroll
        for (int e = 0; e < EE; e++) acc[e] += xv * rw[e*HH + h];
    }
#pragma unroll
    for (int e = 0; e < EE; e++) sp[threadIdx.x][e] = acc[e];
    __syncthreads();
    for (int s = 64; s > 0; s >>= 1) {
        if (threadIdx.x < s)
#pragma unroll
            for (int e = 0; e < EE; e++) sp[threadIdx.x][e] += sp[threadIdx.x + s][e];
        __syncthreads();
    }
    if (threadIdx.x == 0) {
        float lg[EE];
#pragma unroll
        for (int e = 0; e < EE; e++) lg[e] = sp[0][e];
        int i0 = 0;
#pragma unroll
        for (int e = 1; e < EE; e++) if (lg[e] > lg[i0]) i0 = e;
        int i1 = -1;
#pragma unroll
        for (int e = 0; e < EE; e++) {
            if (e == i0) continue;
            if (i1 < 0 || lg[e] > lg[i1]) i1 = e;
        }
        float ex = expf(lg[i1] - lg[i0]);
        g_tok_e[2*t] = i0;  g_tok_e[2*t+1] = i1;
        g_tok_w[2*t] = 1.f/(1.f+ex);  g_tok_w[2*t+1] = ex/(1.f+ex);
        atomicAdd(&g_count[i0], 1);
        atomicAdd(&g_count[i1], 1);
        float m = lg[0];
#pragma unroll
        for (int e = 1; e < EE; e++) m = fmaxf(m, lg[e]);
        float s = 0.f, pe[EE];
#pragma unroll
        for (int e = 0; e < EE; e++) { pe[e] = expf(lg[e] - m); s += pe[e]; }
        float inv = 1.f / s;
#pragma unroll
        for (int e = 0; e < EE; e++) atomicAdd(&g_psum[e], pe[e] * inv);
    }
}

__global__ void setup_kernel(float* __restrict__ out_aux) {
    if (threadIdx.x == 0) {
        int base = 0;
        for (int e = 0; e < EE; e++) {
            g_base[e] = base;
            base += (g_count[e] + BM - 1) & ~(BM - 1);
        }
        g_base[EE] = base;
        float aux = 0.f;
        for (int e = 0; e < EE; e++)
            aux += ((float)g_count[e] / SLOTS) * (g_psum[e] / TT);
        out_aux[0] = aux * EE;
    }
}

__global__ void scatter_kernel() {
    int s = blockIdx.x * blockDim.x + threadIdx.x;
    if (s >= SLOTS) return;
    int e = g_tok_e[s];
    int row = g_base[e] + atomicAdd(&g_fill[e], 1);
    g_sorted_token[row] = s >> 1;
    g_slot_row[s] = row;
}

// ==== GEMM1 (persistent): h1 = silu(x@Wg)*(x@Wu). CTA tile 128M x 64F ====
__global__ __launch_bounds__(256, 2) void gemm1_kernel(
    const float* __restrict__ x, const float* __restrict__ wg, const float* __restrict__ wu)
{
    __shared__ __align__(16) uint2 As[2][8][PIT];
    __shared__ __align__(16) uint2 Bs[2][8][PIT];
    __shared__ int s_tok[128];

    int tid = threadIdx.x, lane = tid & 31, wid = tid >> 5;
    int wm = (wid >> 1) * 32, wn = (wid & 1) * 64;
    int fr = lane >> 2, kq = lane & 3;
    int a_row = tid & 127, a_kh = tid >> 7;
    int b_kp = tid >> 5, b_f = (tid & 31) * 2;

    const int NT = FF / 64;           // 44
    const int total = RT_MAX * NT;    // 3168
    const int chunks = HH / 16;       // 64

    for (int tile = blockIdx.x; tile < total; tile += gridDim.x) {
        int rt = tile % RT_MAX, nt = tile / RT_MAX;
        int r0 = rt * BM;
        if (r0 >= g_base[EE]) continue;
        int n0f = nt * 64;
        int e = 0;
        while (g_base[e+1] <= r0) e++;

        if (tid < 128) s_tok[tid] = g_sorted_token[r0 + tid];
        __syncthreads();

        const float* arow = x + (size_t)s_tok[a_row] * HH + a_kh * 8;
        const float* grow = wg + (size_t)e * HH * FF + n0f + b_f;
        const float* urow = wu + (size_t)e * HH * FF + n0f + b_f;

        float d[2][8][4];
#pragma unroll
        for (int i = 0; i < 2; i++)
#pragma unroll
            for (int j = 0; j < 8; j++)
#pragma unroll
                for (int k = 0; k < 4; k++) d[i][j][k] = 0.f;

#define G1_STS(st, A0, A1, G0, G1v, U0, U1v) do {                               \
    float af_[8] = {(A0).x,(A0).y,(A0).z,(A0).w,(A1).x,(A1).y,(A1).z,(A1).w};   \
    _Pragma("unroll")                                                           \
    for (int j_ = 0; j_ < 4; j_++)                                              \
        As[st][a_kh*4 + j_][a_row] = spb(af_[2*j_], af_[2*j_+1]);               \
    uint2 c0_ = spb((G0).x, (G1v).x);                                           \
    uint2 c1_ = spb((U0).x, (U1v).x);                                           \
    uint2 c2_ = spb((G0).y, (G1v).y);                                           \
    uint2 c3_ = spb((U0).y, (U1v).y);                                           \
    *(uint4*)&Bs[st][b_kp][2*b_f]     = make_uint4(c0_.x, c0_.y, c1_.x, c1_.y); \
    *(uint4*)&Bs[st][b_kp][2*b_f + 2] = make_uint4(c2_.x, c2_.y, c3_.x, c3_.y); \
} while (0)

        {
            float4 a0 = *(const float4*)(arow), a1 = *(const float4*)(arow + 4);
            size_t k0 = (size_t)(2*b_kp) * FF;
            float2 g0 = *(const float2*)(grow + k0), g1 = *(const float2*)(grow + k0 + FF);
            float2 u0 = *(const float2*)(urow + k0), u1 = *(const float2*)(urow + k0 + FF);
            G1_STS(0, a0, a1, g0, g1, u0, u1);
        }
        float4 pa0 = *(const float4*)(arow + 16), pa1 = *(const float4*)(arow + 20);
        float2 pg0, pg1, pu0, pu1;
        {
            size_t k0 = (size_t)(16 + 2*b_kp) * FF;
            pg0 = *(const float2*)(grow + k0);  pg1 = *(const float2*)(grow + k0 + FF);
            pu0 = *(const float2*)(urow + k0);  pu1 = *(const float2*)(urow + k0 + FF);
        }
        __syncthreads();

        for (int c = 0; c < chunks; c++) {
            int s = c & 1;
            if (c + 1 < chunks) {
                int s1 = s ^ 1;
                G1_STS(s1, pa0, pa1, pg0, pg1, pu0, pu1);
            }
            if (c + 2 < chunks) {
                pa0 = *(const float4*)(arow + (c+2)*16);
                pa1 = *(const float4*)(arow + (c+2)*16 + 4);
                size_t k0 = (size_t)((c+2)*16 + 2*b_kp) * FF;
                pg0 = *(const float2*)(grow + k0);  pg1 = *(const float2*)(grow + k0 + FF);
                pu0 = *(const float2*)(urow + k0);  pu1 = *(const float2*)(urow + k0 + FF);
            }
            uint32_t ahi[2][4], alo[2][4];
#pragma unroll
            for (int mt = 0; mt < 2; mt++) {
                int mb = wm + mt*16 + fr;
                uint2 q0 = As[s][kq][mb],   q1 = As[s][kq][mb+8];
                uint2 q2 = As[s][kq+4][mb], q3 = As[s][kq+4][mb+8];
                ahi[mt][0]=q0.x; ahi[mt][1]=q1.x; ahi[mt][2]=q2.x; ahi[mt][3]=q3.x;
                alo[mt][0]=q0.y; alo[mt][1]=q1.y; alo[mt][2]=q2.y; alo[mt][3]=q3.y;
            }
#pragma unroll
            for (int nt2 = 0; nt2 < 8; nt2++) {
                int nn = wn + nt2*8 + fr;
                uint2 b0 = Bs[s][kq][nn], b1 = Bs[s][kq+4][nn];
#pragma unroll
                for (int mt = 0; mt < 2; mt++) {
                    mma_bf16(d[mt][nt2], ahi[mt], b0.x, b1.x);
                    mma_bf16(d[mt][nt2], ahi[mt], b0.y, b1.y);
                    mma_bf16(d[mt][nt2], alo[mt], b0.x, b1.x);
                }
            }
            __syncthreads();
        }
#undef G1_STS

#pragma unroll
        for (int mt = 0; mt < 2; mt++) {
            int row = r0 + wm + mt*16 + fr;
#pragma unroll
            for (int nt2 = 0; nt2 < 8; nt2++) {
                int f = n0f + (wn >> 1) + nt2*4 + kq;
                float gv = d[mt][nt2][0], uv = d[mt][nt2][1];
                g_h1[(size_t)row * FF + f] = (gv / (1.f + expf(-gv))) * uv;
                gv = d[mt][nt2][2]; uv = d[mt][nt2][3];
                g_h1[(size_t)(row + 8) * FF + f] = (gv / (1.f + expf(-gv))) * uv;
            }
        }
    }
}

// ==== GEMM2 (persistent): y = h1 @ Wd. CTA tile 128M x 128N ====
__global__ __launch_bounds__(256, 2) void gemm2_kernel(const float* __restrict__ wd)
{
    __shared__ __align__(16) uint2 As[2][8][PIT];
    __shared__ __align__(16) uint2 Bs[2][8][PIT];

    int tid = threadIdx.x, lane = tid & 31, wid = tid >> 5;
    int wm = (wid >> 1) * 32, wn = (wid & 1) * 64;
    int fr = lane >> 2, kq = lane & 3;
    int a_row = tid & 127, a_kh = tid >> 7;
    int b_kp = tid >> 5, b_n = (tid & 31) * 4;

    const int NT = HH / 128;          // 8
    const int total = RT_MAX * NT;    // 576
    const int chunks = FF / 16;       // 176

    for (int tile = blockIdx.x; tile < total; tile += gridDim.x) {
        int rt = tile % RT_MAX, nt = tile / RT_MAX;
        int r0 = rt * BM;
        if (r0 >= g_base[EE]) continue;
        int n0 = nt * 128;
        int e = 0;
        while (g_base[e+1] <= r0) e++;

        const float* arow = g_h1 + (size_t)(r0 + a_row) * FF + a_kh * 8;
        const float* brow = wd + (size_t)e * FF * HH + n0 + b_n;

        float d[2][8][4];
#pragma unroll
        for (int i = 0; i < 2; i++)
#pragma unroll
            for (int j = 0; j < 8; j++)
#pragma unroll
                for (int k = 0; k < 4; k++) d[i][j][k] = 0.f;

#define G2_STS(st, A0, A1, B0, B1v) do {                                        \
    float af_[8] = {(A0).x,(A0).y,(A0).z,(A0).w,(A1).x,(A1).y,(A1).z,(A1).w};   \
    _Pragma("unroll")                                                           \
    for (int j_ = 0; j_ < 4; j_++)                                              \
        As[st][a_kh*4 + j_][a_row] = spb(af_[2*j_], af_[2*j_+1]);               \
    uint2 c0_ = spb((B0).x, (B1v).x);                                           \
    uint2 c1_ = spb((B0).y, (B1v).y);                                           \
    uint2 c2_ = spb((B0).z, (B1v).z);                                           \
    uint2 c3_ = spb((B0).w, (B1v).w);                                           \
    *(uint4*)&Bs[st][b_kp][b_n]     = make_uint4(c0_.x, c0_.y, c1_.x, c1_.y);   \
    *(uint4*)&Bs[st][b_kp][b_n + 2] = make_uint4(c2_.x, c2_.y, c3_.x, c3_.y);   \
} while (0)

        {
            float4 a0 = *(const float4*)(arow), a1 = *(const float4*)(arow + 4);
            size_t k0 = (size_t)(2*b_kp) * HH;
            float4 b0 = *(const float4*)(brow + k0), b1 = *(const float4*)(brow + k0 + HH);
            G2_STS(0, a0, a1, b0, b1);
        }
        float4 pa0 = *(const float4*)(arow + 16), pa1 = *(const float4*)(arow + 20);
        float4 pb0, pb1;
        {
            size_t k0 = (size_t)(16 + 2*b_kp) * HH;
            pb0 = *(const float4*)(brow + k0);  pb1 = *(const float4*)(brow + k0 + HH);
        }
        __syncthreads();

        for (int c = 0; c < chunks; c++) {
            int s = c & 1;
            if (c + 1 < chunks) {
                int s1 = s ^ 1;
                G2_STS(s1, pa0, pa1, pb0, pb1);
            }
            if (c + 2 < chunks) {
                pa0 = *(const float4*)(arow + (c+2)*16);
                pa1 = *(const float4*)(arow + (c+2)*16 + 4);
                size_t k0 = (size_t)((c+2)*16 + 2*b_kp) * HH;
                pb0 = *(const float4*)(brow + k0);
                pb1 = *(const float4*)(brow + k0 + HH);
            }
            uint32_t ahi[2][4], alo[2][4];
#pragma unroll
            for (int mt = 0; mt < 2; mt++) {
                int mb = wm + mt*16 + fr;
                uint2 q0 = As[s][kq][mb],   q1 = As[s][kq][mb+8];
                uint2 q2 = As[s][kq+4][mb], q3 = As[s][kq+4][mb+8];
                ahi[mt][0]=q0.x; ahi[mt][1]=q1.x; ahi[mt][2]=q2.x; ahi[mt][3]=q3.x;
                alo[mt][0]=q0.y; alo[mt][1]=q1.y; alo[mt][2]=q2.y; alo[mt][3]=q3.y;
            }
#pragma unroll
            for (int nt2 = 0; nt2 < 8; nt2++) {
                int nn = wn + nt2*8 + fr;
                uint2 b0 = Bs[s][kq][nn], b1 = Bs[s][kq+4][nn];
#pragma unroll
                for (int mt = 0; mt < 2; mt++) {
                    mma_bf16(d[mt][nt2], ahi[mt], b0.x, b1.x);
                    mma_bf16(d[mt][nt2], ahi[mt], b0.y, b1.y);
                    mma_bf16(d[mt][nt2], alo[mt], b0.x, b1.x);
                }
            }
            __syncthreads();
        }
#undef G2_STS

#pragma unroll
        for (int mt = 0; mt < 2; mt++) {
            int row = r0 + wm + mt*16 + fr;
#pragma unroll
            for (int nt2 = 0; nt2 < 8; nt2++) {
                int col = n0 + wn + nt2*8 + 2*kq;
                *(float2*)&g_y[(size_t)row * HH + col]       = make_float2(d[mt][nt2][0], d[mt][nt2][1]);
                *(float2*)&g_y[(size_t)(row + 8) * HH + col] = make_float2(d[mt][nt2][2], d[mt][nt2][3]);
            }
        }
    }
}

__global__ void combine_kernel(float* __restrict__ out) {
    int i = blockIdx.x * blockDim.x + threadIdx.x;
    if (i >= TT * (HH/4)) return;
    int t = i / (HH/4);
    int c = (i - t * (HH/4)) * 4;
    int r0 = g_slot_row[2*t], r1 = g_slot_row[2*t+1];
    float w0 = g_tok_w[2*t], w1 = g_tok_w[2*t+1];
    float4 y0 = *(const float4*)(g_y + (size_t)r0 * HH + c);
    float4 y1 = *(const float4*)(g_y + (size_t)r1 * HH + c);
    float4 o;
    o.x = w0*y0.x + w1*y1.x;  o.y = w0*y0.y + w1*y1.y;
    o.z = w0*y0.z + w1*y1.z;  o.w = w0*y0.w + w1*y1.w;
    *(float4*)(out + (size_t)t * HH + c) = o;
}

extern "C" void kernel_launch(void* const* d_in, const int* in_sizes, int n_in,
                              void* d_out, int out_size) {
    const float* x  = (const float*)d_in[0];
    const float* rw = (const float*)d_in[1];
    const float* wg = (const float*)d_in[2];
    const float* wu = (const float*)d_in[3];
    const float* wd = (const float*)d_in[4];
    float* out = (float*)d_out;

    init_kernel<<<(PADMAX + 255) / 256, 256>>>();
    router_kernel<<<TT, 128>>>(x, rw);
    setup_kernel<<<1, 32>>>(out + (size_t)TT * HH);
    scatter_kernel<<<(SLOTS + 255) / 256, 256>>>();
    gemm1_kernel<<<GRID_P, 256>>>(x, wg, wu);
    gemm2_kernel<<<GRID_P, 256>>>(wd);
    combine_kernel<<<(TT * (HH/4) + 255) / 256, 256>>>(out);
}